// round 1
// baseline (speedup 1.0000x reference)
#include <cuda_runtime.h>

// Problem constants (DgaRawSequence: B=256, T=8192, I=6, U=64, M=16)
#define NB 256
#define NT 8192
#define NI 6
#define NU 64
#define NM 16
#define UNFOLDS 6
#define EPSV 1e-8f
#define LOG2E 1.4426950408889634f

__device__ __forceinline__ float ex2f_(float v) {
    float y; asm("ex2.approx.f32 %0, %1;" : "=f"(y) : "f"(v)); return y;
}
__device__ __forceinline__ float rcpf_(float v) {
    float y; asm("rcp.approx.f32 %0, %1;" : "=f"(y) : "f"(v)); return y;
}

// Block = 256 threads = 64 u-neurons x 4 j-chunks (16 presynaptic j each).
// tid = u*4 + c ; lanes of one u are contiguous -> shfl.xor(1),(2) reduces over c.
// One block per batch element; whole T=8192 scan runs inside the block.
__global__ void __launch_bounds__(256, 2) ltc_seq_kernel(
    const float* __restrict__ x,
    const float* __restrict__ gleak, const float* __restrict__ vleak,
    const float* __restrict__ cm,
    const float* __restrict__ sigma, const float* __restrict__ mu,
    const float* __restrict__ w,     const float* __restrict__ erev,
    const float* __restrict__ ssigma, const float* __restrict__ smu,
    const float* __restrict__ swv,    const float* __restrict__ serev,
    const float* __restrict__ in_w,  const float* __restrict__ in_b,
    const float* __restrict__ out_w, const float* __restrict__ out_b,
    float* __restrict__ out)
{
    const int tid = threadIdx.x;
    const int u   = tid >> 2;
    const int c   = tid & 3;
    const int b   = blockIdx.x;

    __shared__ __align__(16) float vbuf[2][NU];

    // ---- per-(j,u) recurrent params in registers, j = 16*c + k ----
    float p_na[16], p_tb[16], p_w[16], p_we[16];
#pragma unroll
    for (int k = 0; k < 16; k++) {
        int j = c * 16 + k;
        float sg = sigma[j * NU + u];
        float m  = mu[j * NU + u];
        float ww = w[j * NU + u];
        float er = erev[j * NU + u];
        // t = (mu - v)*sigma*log2e  -> exp(-(v-mu)*sigma) = 2^t
        p_na[k] = -sg * LOG2E;          // multiplies v
        p_tb[k] =  m * sg * LOG2E;      // constant term
        p_w[k]  =  ww;
        p_we[k] =  ww * er;
    }

    // ---- sensory params: lane c handles i0=c and i1=c+4 (if < NI) ----
    const int i0 = c;
    const int i1 = c + 4;
    const bool has1 = (i1 < NI);
    float s_na0, s_tb0, s_w0, s_we0, iw0, ib0;
    float s_na1 = 0.f, s_tb1 = 0.f, s_w1 = 0.f, s_we1 = 0.f, iw1 = 0.f, ib1 = 0.f;
    {
        float sg = ssigma[i0 * NU + u], m = smu[i0 * NU + u];
        float ww = swv[i0 * NU + u],    er = serev[i0 * NU + u];
        s_na0 = -sg * LOG2E; s_tb0 = m * sg * LOG2E;
        s_w0 = ww; s_we0 = ww * er;
        iw0 = in_w[i0]; ib0 = in_b[i0];
    }
    if (has1) {
        float sg = ssigma[i1 * NU + u], m = smu[i1 * NU + u];
        float ww = swv[i1 * NU + u],    er = serev[i1 * NU + u];
        s_na1 = -sg * LOG2E; s_tb1 = m * sg * LOG2E;
        s_w1 = ww; s_we1 = ww * er;
        iw1 = in_w[i1]; ib1 = in_b[i1];
    }

    // ---- per-u constants ----
    const float cmt  = 6.0f * cm[u];     // cm / (elapsed/unfolds)
    const float gl   = gleak[u];
    const float glvl = gl * vleak[u];
    float ow = 0.f, ob = 0.f;
    if (u < NM) { ow = out_w[u]; ob = out_b[u]; }

    // ---- init state v = 0 ----
    if (tid < NU) vbuf[0][tid] = 0.f;
    __syncthreads();

    const float* xb   = x   + (size_t)b * NT * NI;
    float*       outb = out + (size_t)b * NT * NM;

    // prefetch x for t=0
    float xv0 = xb[i0];
    float xv1 = has1 ? xb[i1] : 0.f;

    for (int t = 0; t < NT; t++) {
        // ---- sensory sums (constant across unfolds) ----
        float ds, ns;
        {
            float xi = fmaf(xv0, iw0, ib0);
            float tt = fmaf(xi, s_na0, s_tb0);
            float r  = rcpf_(1.0f + ex2f_(tt));
            ds = s_w0 * r;
            ns = s_we0 * r;
            if (has1) {
                float xi1 = fmaf(xv1, iw1, ib1);
                float tt1 = fmaf(xi1, s_na1, s_tb1);
                float r1  = rcpf_(1.0f + ex2f_(tt1));
                ds = fmaf(s_w1, r1, ds);
                ns = fmaf(s_we1, r1, ns);
            }
        }
        ns += __shfl_xor_sync(0xffffffffu, ns, 1);
        ds += __shfl_xor_sync(0xffffffffu, ds, 1);
        ns += __shfl_xor_sync(0xffffffffu, ns, 2);
        ds += __shfl_xor_sync(0xffffffffu, ds, 2);

        // ---- prefetch next timestep's x while unfolds run ----
        if (t + 1 < NT) {
            xv0 = xb[(t + 1) * NI + i0];
            if (has1) xv1 = xb[(t + 1) * NI + i1];
        }

        float vlast = 0.f;
        // 6 unfolds fully unrolled: even s reads buf0/writes buf1, odd s the reverse.
#pragma unroll
        for (int s = 0; s < UNFOLDS; s++) {
            const int rb = s & 1;
            const float* vp = vbuf[rb];

            const float4* vp4 = (const float4*)(vp + c * 16);
            float4 q0 = vp4[0], q1 = vp4[1], q2 = vp4[2], q3 = vp4[3];
            float vj[16];
            vj[0]=q0.x; vj[1]=q0.y; vj[2]=q0.z; vj[3]=q0.w;
            vj[4]=q1.x; vj[5]=q1.y; vj[6]=q1.z; vj[7]=q1.w;
            vj[8]=q2.x; vj[9]=q2.y; vj[10]=q2.z; vj[11]=q2.w;
            vj[12]=q3.x; vj[13]=q3.y; vj[14]=q3.z; vj[15]=q3.w;

            float den0 = 0.f, den1 = 0.f, num0 = 0.f, num1 = 0.f;
#pragma unroll
            for (int k = 0; k < 16; k++) {
                float tt = fmaf(vj[k], p_na[k], p_tb[k]);
                float r  = rcpf_(1.0f + ex2f_(tt));   // sigmoid((v-mu)*sigma)
                if (k & 1) {
                    den1 = fmaf(p_w[k],  r, den1);
                    num1 = fmaf(p_we[k], r, num1);
                } else {
                    den0 = fmaf(p_w[k],  r, den0);
                    num0 = fmaf(p_we[k], r, num0);
                }
            }
            float num = num0 + num1;
            float den = den0 + den1;
            num += __shfl_xor_sync(0xffffffffu, num, 1);
            den += __shfl_xor_sync(0xffffffffu, den, 1);
            num += __shfl_xor_sync(0xffffffffu, num, 2);
            den += __shfl_xor_sync(0xffffffffu, den, 2);

            if (c == 0) {
                float vu = vp[u];
                float nn = fmaf(cmt, vu, glvl) + num + ns;
                float dd = cmt + gl + den + ds + EPSV;
                float r  = rcpf_(dd);
                r = fmaf(r, fmaf(-dd, r, 1.0f), r);   // 1 Newton step on rcp
                float vn = nn * r;
                vbuf[rb ^ 1][u] = vn;
                vlast = vn;
            }
            __syncthreads();
        }

        // ---- output: first M motor neurons, affine ----
        if (c == 0 && u < NM) {
            outb[t * NM + u] = fmaf(vlast, ow, ob);
        }
    }
}

extern "C" void kernel_launch(void* const* d_in, const int* in_sizes, int n_in,
                              void* d_out, int out_size) {
    (void)in_sizes; (void)n_in; (void)out_size;
    const float* xx     = (const float*)d_in[0];
    const float* gleak  = (const float*)d_in[1];
    const float* vleak  = (const float*)d_in[2];
    const float* cm     = (const float*)d_in[3];
    const float* sigma  = (const float*)d_in[4];
    const float* mu     = (const float*)d_in[5];
    const float* w      = (const float*)d_in[6];
    const float* erev   = (const float*)d_in[7];
    const float* ssig   = (const float*)d_in[8];
    const float* smu    = (const float*)d_in[9];
    const float* sw     = (const float*)d_in[10];
    const float* serev  = (const float*)d_in[11];
    const float* in_w   = (const float*)d_in[12];
    const float* in_b   = (const float*)d_in[13];
    const float* out_w  = (const float*)d_in[14];
    const float* out_b  = (const float*)d_in[15];
    float* out = (float*)d_out;

    ltc_seq_kernel<<<NB, 256>>>(xx, gleak, vleak, cm, sigma, mu, w, erev,
                                ssig, smu, sw, serev, in_w, in_b, out_w, out_b,
                                out);
}

// round 2
// speedup vs baseline: 1.6365x; 1.6365x over previous
#include <cuda_runtime.h>

// Problem constants (DgaRawSequence: B=256, T=8192, I=6, U=64, M=16)
#define NB 256
#define NT 8192
#define NI 6
#define NU 64
#define NM 16
#define UNFOLDS 6
#define EPSV 1e-8f

__device__ __forceinline__ float tanhf_(float v) {
    float y; asm("tanh.approx.f32 %0, %1;" : "=f"(y) : "f"(v)); return y;
}
__device__ __forceinline__ float rcpf_(float v) {
    float y; asm("rcp.approx.f32 %0, %1;" : "=f"(y) : "f"(v)); return y;
}

// sigmoid(z) = 0.5 + 0.5*tanh(z/2); the 0.5's are folded into the weights:
//   w * sigmoid((v-mu)*sg) = (w/2) + (w/2)*tanh( v*(sg/2) - mu*sg/2 )
// so each synapse costs 1 FMA (arg) + 1 MUFU (tanh) + 2 FMA (num/den accum),
// with the constant (w/2) terms pre-summed into per-thread bases.
//
// Block = 256 threads = 64 u-neurons x 4 j-chunks (16 presynaptic j each).
// tid = u*4 + c ; lanes of one u are contiguous -> shfl.xor(1),(2) reduces over c.
// One block per batch element; whole T=8192 scan runs inside the block.
__global__ void __launch_bounds__(256, 2) ltc_seq_kernel(
    const float* __restrict__ x,
    const float* __restrict__ gleak, const float* __restrict__ vleak,
    const float* __restrict__ cm,
    const float* __restrict__ sigma, const float* __restrict__ mu,
    const float* __restrict__ w,     const float* __restrict__ erev,
    const float* __restrict__ ssigma, const float* __restrict__ smu,
    const float* __restrict__ swv,    const float* __restrict__ serev,
    const float* __restrict__ in_w,  const float* __restrict__ in_b,
    const float* __restrict__ out_w, const float* __restrict__ out_b,
    float* __restrict__ out)
{
    const int tid = threadIdx.x;
    const int u   = tid >> 2;
    const int c   = tid & 3;
    const int b   = blockIdx.x;

    __shared__ __align__(16) float vbuf[2][NU];

    // ---- per-(j,u) recurrent params in registers, j = 16*c + k ----
    float p_na[16], p_tb[16], p_wh[16], p_weh[16];
    float denb = 0.f, numb = 0.f;   // sum of (w/2), (w*erev/2) bases
#pragma unroll
    for (int k = 0; k < 16; k++) {
        int j = c * 16 + k;
        float sg = sigma[j * NU + u];
        float m  = mu[j * NU + u];
        float ww = w[j * NU + u];
        float er = erev[j * NU + u];
        p_na[k]  = 0.5f * sg;            // multiplies v   (z/2)
        p_tb[k]  = -0.5f * m * sg;       // constant term
        p_wh[k]  = 0.5f * ww;
        p_weh[k] = 0.5f * ww * er;
        denb += p_wh[k];
        numb += p_weh[k];
    }

    // ---- sensory params: lane c handles i0=c and i1=c+4 (if < NI) ----
    const int i0 = c;
    const int i1 = c + 4;
    const bool has1 = (i1 < NI);
    float s_na0, s_tb0, s_wh0, s_weh0, iw0, ib0;
    float s_na1 = 0.f, s_tb1 = 0.f, s_wh1 = 0.f, s_weh1 = 0.f, iw1 = 0.f, ib1 = 0.f;
    float s_denb = 0.f, s_numb = 0.f;
    {
        float sg = ssigma[i0 * NU + u], m = smu[i0 * NU + u];
        float ww = swv[i0 * NU + u],    er = serev[i0 * NU + u];
        s_na0 = 0.5f * sg; s_tb0 = -0.5f * m * sg;
        s_wh0 = 0.5f * ww; s_weh0 = 0.5f * ww * er;
        s_denb += s_wh0; s_numb += s_weh0;
        iw0 = in_w[i0]; ib0 = in_b[i0];
    }
    if (has1) {
        float sg = ssigma[i1 * NU + u], m = smu[i1 * NU + u];
        float ww = swv[i1 * NU + u],    er = serev[i1 * NU + u];
        s_na1 = 0.5f * sg; s_tb1 = -0.5f * m * sg;
        s_wh1 = 0.5f * ww; s_weh1 = 0.5f * ww * er;
        s_denb += s_wh1; s_numb += s_weh1;
        iw1 = in_w[i1]; ib1 = in_b[i1];
    }

    // ---- per-u constants ----
    const float cmt  = 6.0f * cm[u];     // cm / (elapsed/unfolds)
    const float gl   = gleak[u];
    const float glvl = gl * vleak[u];
    float ow = 0.f, ob = 0.f;
    if (u < NM) { ow = out_w[u]; ob = out_b[u]; }

    // ---- init state v = 0 ----
    if (tid < NU) vbuf[0][tid] = 0.f;
    __syncthreads();

    const float* xb   = x   + (size_t)b * NT * NI;
    float*       outb = out + (size_t)b * NT * NM;

    // prefetch x for t=0
    float xv0 = xb[i0];
    float xv1 = has1 ? xb[i1] : 0.f;

    for (int t = 0; t < NT; t++) {
        // ---- sensory sums (constant across unfolds) ----
        float ds, ns;
        {
            float xi = fmaf(xv0, iw0, ib0);
            float th = tanhf_(fmaf(xi, s_na0, s_tb0));
            ds = fmaf(s_wh0,  th, s_denb);
            ns = fmaf(s_weh0, th, s_numb);
            if (has1) {
                float xi1 = fmaf(xv1, iw1, ib1);
                float th1 = tanhf_(fmaf(xi1, s_na1, s_tb1));
                ds = fmaf(s_wh1,  th1, ds);
                ns = fmaf(s_weh1, th1, ns);
            }
        }
        ns += __shfl_xor_sync(0xffffffffu, ns, 1);
        ds += __shfl_xor_sync(0xffffffffu, ds, 1);
        ns += __shfl_xor_sync(0xffffffffu, ns, 2);
        ds += __shfl_xor_sync(0xffffffffu, ds, 2);

        // ---- prefetch next timestep's x while unfolds run ----
        if (t + 1 < NT) {
            xv0 = xb[(t + 1) * NI + i0];
            if (has1) xv1 = xb[(t + 1) * NI + i1];
        }

        float vlast = 0.f;
        // 6 unfolds fully unrolled: even s reads buf0/writes buf1, odd s the reverse.
#pragma unroll
        for (int s = 0; s < UNFOLDS; s++) {
            const int rb = s & 1;
            const float* vp = vbuf[rb];

            const float4* vp4 = (const float4*)(vp + c * 16);
            float4 q0 = vp4[0], q1 = vp4[1], q2 = vp4[2], q3 = vp4[3];
            float vj[16];
            vj[0]=q0.x; vj[1]=q0.y; vj[2]=q0.z; vj[3]=q0.w;
            vj[4]=q1.x; vj[5]=q1.y; vj[6]=q1.z; vj[7]=q1.w;
            vj[8]=q2.x; vj[9]=q2.y; vj[10]=q2.z; vj[11]=q2.w;
            vj[12]=q3.x; vj[13]=q3.y; vj[14]=q3.z; vj[15]=q3.w;

            // two accumulator pairs for ILP; bases folded into pair 0
            float den0 = denb, den1 = 0.f, num0 = numb, num1 = 0.f;
#pragma unroll
            for (int k = 0; k < 16; k++) {
                float th = tanhf_(fmaf(vj[k], p_na[k], p_tb[k]));
                if (k & 1) {
                    den1 = fmaf(p_wh[k],  th, den1);
                    num1 = fmaf(p_weh[k], th, num1);
                } else {
                    den0 = fmaf(p_wh[k],  th, den0);
                    num0 = fmaf(p_weh[k], th, num0);
                }
            }
            float num = num0 + num1;
            float den = den0 + den1;
            num += __shfl_xor_sync(0xffffffffu, num, 1);
            den += __shfl_xor_sync(0xffffffffu, den, 1);
            num += __shfl_xor_sync(0xffffffffu, num, 2);
            den += __shfl_xor_sync(0xffffffffu, den, 2);

            if (c == 0) {
                float vu = vp[u];
                float nn = fmaf(cmt, vu, glvl) + num + ns;
                float dd = cmt + gl + den + ds + EPSV;
                float r  = rcpf_(dd);
                r = fmaf(r, fmaf(-dd, r, 1.0f), r);   // 1 Newton step on rcp
                float vn = nn * r;
                vbuf[rb ^ 1][u] = vn;
                vlast = vn;
            }
            __syncthreads();
        }

        // ---- output: first M motor neurons, affine ----
        if (c == 0 && u < NM) {
            outb[t * NM + u] = fmaf(vlast, ow, ob);
        }
    }
}

extern "C" void kernel_launch(void* const* d_in, const int* in_sizes, int n_in,
                              void* d_out, int out_size) {
    (void)in_sizes; (void)n_in; (void)out_size;
    const float* xx     = (const float*)d_in[0];
    const float* gleak  = (const float*)d_in[1];
    const float* vleak  = (const float*)d_in[2];
    const float* cm     = (const float*)d_in[3];
    const float* sigma  = (const float*)d_in[4];
    const float* mu     = (const float*)d_in[5];
    const float* w      = (const float*)d_in[6];
    const float* erev   = (const float*)d_in[7];
    const float* ssig   = (const float*)d_in[8];
    const float* smu    = (const float*)d_in[9];
    const float* sw     = (const float*)d_in[10];
    const float* serev  = (const float*)d_in[11];
    const float* in_w   = (const float*)d_in[12];
    const float* in_b   = (const float*)d_in[13];
    const float* out_w  = (const float*)d_in[14];
    const float* out_b  = (const float*)d_in[15];
    float* out = (float*)d_out;

    ltc_seq_kernel<<<NB, 256>>>(xx, gleak, vleak, cm, sigma, mu, w, erev,
                                ssig, smu, sw, serev, in_w, in_b, out_w, out_b,
                                out);
}